// round 14
// baseline (speedup 1.0000x reference)
#include <cuda_runtime.h>
#include <cstdint>

// CustomRNN: h_t = W2 h_{t-1} + x_t w1 ; y_t = W3 h_t
// => causal conv y[b,t] = sum_k u_k x[b,t-k], u_k = W3 W2^k w1, KC=24.
// 4 graph-captured launches:
//  K1: P2=W2^2           | v0=w1, v1=W2 w1
//  K2: P4=P2^2 (+P4^T)   | v2,v3 = P2{v0,v1}
//  K3: 8 blocks: block j chains v_j -> v_{j+8} -> v_{j+16} via coalesced
//      P4^T hops (block-local), computes taps u_{j},u_{j+8},u_{j+16} = W3 v
//  K4: conv, smem-staged coalesced output stores

#define BB   64
#define TT   8192
#define HH   256
#define OUTD 10
#define KC   24
#define TBc  1024
#define GP   260

typedef unsigned long long ull;

// ---- device scratch ----
__device__ __align__(16) float g_P2[HH * HH];
__device__ __align__(16) float g_P4[HH * HH];
__device__ __align__(16) float g_P4T[HH * HH];
__device__ __align__(16) float g_V[4][HH];      // v0..v3
__device__ __align__(16) float g_U[KC][OUTD];   // 240 floats = 120 u64

// ---- packed f32x2 helpers ----
__device__ __forceinline__ ull fma2(ull a, ull b, ull c) {
    ull d;
    asm("fma.rn.f32x2 %0, %1, %2, %3;" : "=l"(d) : "l"(a), "l"(b), "l"(c));
    return d;
}
__device__ __forceinline__ ull pack_dup(float x) {
    ull d; unsigned u = __float_as_uint(x);
    asm("mov.b64 %0, {%1, %1};" : "=l"(d) : "r"(u));
    return d;
}
__device__ __forceinline__ float2 unpack2(ull a) {
    float2 f;
    asm("mov.b64 {%0, %1}, %2;" : "=f"(f.x), "=f"(f.y) : "l"(a));
    return f;
}

// ---- 32x32-tile GEMM square: C = X @ X ; optionally also C^T ----
template <bool WRITE_T>
__device__ void gemm_tile(const float* __restrict__ X, float* C, float* CT,
                          int bid, float* sm)
{
    float* Xr = sm;                // [32][GP]
    float* Xc = sm + 32 * GP;      // [256][32]
    const int tid = threadIdx.x;
    const int i0 = (bid >> 3) * 32;
    const int j0 = (bid & 7) * 32;

    for (int n = tid; n < 32 * 256; n += 256) {
        int rr = n >> 8, kk = n & 255;
        Xr[rr * GP + kk] = __ldg(X + (i0 + rr) * HH + kk);
    }
    for (int n = tid; n < 256 * 32; n += 256) {
        int kk = n >> 5, jj = n & 31;
        Xc[kk * 32 + jj] = __ldg(X + kk * HH + j0 + jj);
    }
    __syncthreads();

    const int r0 = (tid >> 4) * 2;
    const int c0 = (tid & 15) * 2;
    ull q0 = 0ull, q1 = 0ull;
#pragma unroll 8
    for (int k = 0; k < 256; ++k) {
        ull cp = *reinterpret_cast<const ull*>(&Xc[k * 32 + c0]);
        ull a0 = pack_dup(Xr[r0 * GP + k]);
        ull a1 = pack_dup(Xr[(r0 + 1) * GP + k]);
        q0 = fma2(a0, cp, q0);
        q1 = fma2(a1, cp, q1);
    }
    float2 f0 = unpack2(q0), f1 = unpack2(q1);
    *reinterpret_cast<float2*>(&C[(i0 + r0) * HH + j0 + c0]) = f0;
    *reinterpret_cast<float2*>(&C[(i0 + r0 + 1) * HH + j0 + c0]) = f1;

    if (WRITE_T) {
        // transpose tile through smem, then coalesced float4 stores
        float* T = sm;   // reuse Xr region: [32][33]
        __syncthreads();
        T[(c0    ) * 33 + r0    ] = f0.x;
        T[(c0 + 1) * 33 + r0    ] = f0.y;
        T[(c0    ) * 33 + r0 + 1] = f1.x;
        T[(c0 + 1) * 33 + r0 + 1] = f1.y;
        __syncthreads();
        int row = tid >> 3, col = (tid & 7) * 4;
        float4 v = make_float4(T[row * 33 + col],     T[row * 33 + col + 1],
                               T[row * 33 + col + 2], T[row * 33 + col + 3]);
        *reinterpret_cast<float4*>(&CT[(j0 + row) * HH + i0 + col]) = v;
    }
}

// ---- 32-row matvec slice with prefetch: vout[row0..row0+31] = M @ vin ----
__device__ void matvec32(const float* __restrict__ M,
                         const float* __restrict__ vin,
                         float* __restrict__ vout, int row0)
{
    const int w = threadIdx.x >> 5, l = threadIdx.x & 31;
    const float4* vp = reinterpret_cast<const float4*>(vin);
    float4 va = __ldg(vp + l);
    float4 vb = __ldg(vp + 32 + l);
    float4 ma[4], mb[4];
#pragma unroll
    for (int rr = 0; rr < 4; ++rr) {
        const float4* mp =
            reinterpret_cast<const float4*>(M + (row0 + w + rr * 8) * HH);
        ma[rr] = __ldg(mp + l);
        mb[rr] = __ldg(mp + 32 + l);
    }
    float p[4];
#pragma unroll
    for (int rr = 0; rr < 4; ++rr)
        p[rr] = ma[rr].x * va.x + ma[rr].y * va.y + ma[rr].z * va.z + ma[rr].w * va.w
              + mb[rr].x * vb.x + mb[rr].y * vb.y + mb[rr].z * vb.z + mb[rr].w * vb.w;
#pragma unroll
    for (int off = 16; off; off >>= 1)
#pragma unroll
        for (int rr = 0; rr < 4; ++rr)
            p[rr] += __shfl_xor_sync(0xffffffffu, p[rr], off);
    if (l == 0) {
#pragma unroll
        for (int rr = 0; rr < 4; ++rr) vout[row0 + w + rr * 8] = p[rr];
    }
}

// ---- K1/K2: GEMM square + seed matvecs ----
#define GEMM_SMEM_BYTES ((32 * GP + 256 * 32) * 4)

extern "C" __global__ void __launch_bounds__(256, 2)
gemm_seed_kernel(const float* __restrict__ W2,
                 const float* __restrict__ W1, int phase)
{
    extern __shared__ float sm[];
    const int bid = blockIdx.x;

    if (phase == 0) {
        if (bid < 64) gemm_tile<false>(W2, g_P2, nullptr, bid, sm);
        else {
            if (bid == 64) g_V[0][threadIdx.x] = __ldg(W1 + threadIdx.x);
            matvec32(W2, W1, &g_V[1][0], (bid - 64) * 32);
        }
    } else {
        if (bid < 64) gemm_tile<true>(g_P2, g_P4, g_P4T, bid, sm);
        else {
            int s = (bid - 64) >> 3;
            matvec32(g_P2, &g_V[s][0], &g_V[2 + s][0], ((bid - 64) & 7) * 32);
        }
    }
}

// ---- K3: 8 blocks; block j chains and emits taps u_j, u_{j+8}, u_{j+16} ----
// hop: dst[t] = sum_c P4T[c*HH+t] * src[c]   (coalesced LDG, smem broadcast)
extern "C" __global__ void __launch_bounds__(256)
chain_taps_kernel(const float* __restrict__ W3)
{
    __shared__ __align__(16) float vsm[3][HH];
    __shared__ __align__(16) float tbuf[HH];
    const int tid = threadIdx.x;
    const int j = blockIdx.x;
    const int w = tid >> 5, l = tid & 31;

    // stage A: vsm[0] = v_j
    if (j < 4) {
        vsm[0][tid] = __ldg(&g_V[j][tid]);
    } else {
        tbuf[tid] = __ldg(&g_V[j - 4][tid]);
        __syncthreads();
        float acc = 0.f;
#pragma unroll 8
        for (int c = 0; c < HH; ++c)
            acc = fmaf(__ldg(g_P4T + c * HH + tid), tbuf[c], acc);
        vsm[0][tid] = acc;
    }
    __syncthreads();

    // stages B, C: two hops each
#pragma unroll
    for (int s = 0; s < 2; ++s) {
        float acc = 0.f;
#pragma unroll 8
        for (int c = 0; c < HH; ++c)
            acc = fmaf(__ldg(g_P4T + c * HH + tid), vsm[s][c], acc);
        tbuf[tid] = acc;
        __syncthreads();
        acc = 0.f;
#pragma unroll 8
        for (int c = 0; c < HH; ++c)
            acc = fmaf(__ldg(g_P4T + c * HH + tid), tbuf[c], acc);
        vsm[s + 1][tid] = acc;
        __syncthreads();
    }

    // taps: 30 warp-dots (4 per warp), u_{j+8g}[o] = W3[o] . vsm[g]
#pragma unroll
    for (int i = 0; i < 4; ++i) {
        int d = w * 4 + i;
        if (d < 30) {
            int g = d / 10, o = d - g * 10;
            const float4* W4 = reinterpret_cast<const float4*>(W3 + o * HH);
            const float4* V4 = reinterpret_cast<const float4*>(&vsm[g][0]);
            float4 a = __ldg(W4 + l), b = __ldg(W4 + 32 + l);
            float4 va = V4[l], vb = V4[32 + l];
            float p = a.x * va.x + a.y * va.y + a.z * va.z + a.w * va.w
                    + b.x * vb.x + b.y * vb.y + b.z * vb.z + b.w * vb.w;
#pragma unroll
            for (int off = 16; off; off >>= 1)
                p += __shfl_xor_sync(0xffffffffu, p, off);
            if (l == 0) g_U[j + 8 * g][o] = p;
        }
    }
}

// ---- K4: conv. grid (8, 64) x 256 threads, 4 t/thread, staged stores ----
extern "C" __global__ void __launch_bounds__(256)
conv_kernel(const float* __restrict__ x, float* __restrict__ y)
{
    __shared__ __align__(16) float xs[TBc + KC];   // 1047 used
    __shared__ __align__(16) ull us[KC * 5];       // 120 tap pairs
    __shared__ __align__(16) float ys[TBc * OUTD]; // 40KB staged output

    const int tid = threadIdx.x;
    const int b   = blockIdx.y;
    const int t0  = blockIdx.x * TBc;

    if (tid < KC * 5)
        us[tid] = __ldg(reinterpret_cast<const ull*>(&g_U[0][0]) + tid);

    const float* xb = x + (size_t)b * TT;
    for (int i = tid; i < TBc + KC - 1; i += 256) {
        int gi = t0 - (KC - 1) + i;
        xs[i] = (gi >= 0) ? __ldg(xb + gi) : 0.f;
    }
    __syncthreads();

    ull a[4][5];
#pragma unroll
    for (int j = 0; j < 4; ++j)
#pragma unroll
        for (int p = 0; p < 5; ++p) a[j][p] = 0ull;

#pragma unroll 4
    for (int k = 0; k < KC; ++k) {
        ull u0 = us[k * 5 + 0], u1 = us[k * 5 + 1], u2 = us[k * 5 + 2];
        ull u3 = us[k * 5 + 3], u4 = us[k * 5 + 4];
#pragma unroll
        for (int j = 0; j < 4; ++j) {
            ull xv = pack_dup(xs[tid + j * 256 + (KC - 1) - k]);
            a[j][0] = fma2(xv, u0, a[j][0]);
            a[j][1] = fma2(xv, u1, a[j][1]);
            a[j][2] = fma2(xv, u2, a[j][2]);
            a[j][3] = fma2(xv, u3, a[j][3]);
            a[j][4] = fma2(xv, u4, a[j][4]);
        }
    }

    // stage into smem (2-way bank conflicts tolerable), then coalesced STG.128
#pragma unroll
    for (int j = 0; j < 4; ++j) {
        float2* yp = reinterpret_cast<float2*>(&ys[(tid + j * 256) * OUTD]);
#pragma unroll
        for (int p = 0; p < 5; ++p) yp[p] = unpack2(a[j][p]);
    }
    __syncthreads();

    float4* yg = reinterpret_cast<float4*>(y + ((size_t)b * TT + t0) * OUTD);
    const float4* ysrc = reinterpret_cast<const float4*>(ys);
#pragma unroll
    for (int i = 0; i < (TBc * OUTD) / (256 * 4); ++i)
        yg[tid + i * 256] = ysrc[tid + i * 256];
}

// ---------------------------------------------------------------------------
extern "C" void kernel_launch(void* const* d_in, const int* in_sizes, int n_in,
                              void* d_out, int out_size)
{
    const float *x = nullptr, *W1 = nullptr, *W2 = nullptr, *W3 = nullptr;
    for (int idx = 0; idx < n_in; ++idx) {
        int s = in_sizes[idx];
        const float* p = (const float*)d_in[idx];
        if      (s == BB * TT)   x  = p;
        else if (s == HH)        W1 = p;
        else if (s == HH * HH)   W2 = p;
        else if (s == OUTD * HH) W3 = p;
    }

    cudaFuncSetAttribute(gemm_seed_kernel,
                         cudaFuncAttributeMaxDynamicSharedMemorySize,
                         GEMM_SMEM_BYTES);

    gemm_seed_kernel<<<72, 256, GEMM_SMEM_BYTES>>>(W2, W1, 0); // P2 | v0,v1
    gemm_seed_kernel<<<80, 256, GEMM_SMEM_BYTES>>>(W2, W1, 1); // P4,P4T | v2,v3
    chain_taps_kernel<<<8, 256>>>(W3);                          // g_U
    conv_kernel<<<dim3(TT / TBc, BB, 1), 256>>>(x, (float*)d_out);
}